// round 1
// baseline (speedup 1.0000x reference)
#include <cuda_runtime.h>

// Problem constants (fixed by the reference)
#define BB 4
#define CC 256
#define HH 56
#define WW 56
#define CR 64          // C / 4
#define GG 16          // groups = C / GC
#define GC 16
#define KK 7
#define K2 49
#define HW (HH * WW)   // 3136
#define PAD 3

// Scratch (allocation-free rule: __device__ globals)
__device__ float g_w1[BB * CR * HW];            // conv1+bn+relu output: [B,Cr,H,W]
__device__ float g_w2[BB * GG * K2 * HW];       // conv2 output: [B, G*K2, H, W]

// ---------------------------------------------------------------------------
// Kernel 1: w1 = relu(bn(conv1_1x1(x)))
// one thread per output element [B,Cr,H,W]; inner loop over C=256
// ---------------------------------------------------------------------------
__global__ void k1_conv1_bn_relu(const float* __restrict__ x,
                                 const float* __restrict__ w1w,
                                 const float* __restrict__ gamma,
                                 const float* __restrict__ beta,
                                 const float* __restrict__ mean,
                                 const float* __restrict__ var) {
    int idx = blockIdx.x * blockDim.x + threadIdx.x;
    if (idx >= BB * CR * HW) return;
    int hw = idx % HW;
    int o  = (idx / HW) % CR;
    int b  = idx / (CR * HW);

    const float* xb = x + (size_t)b * CC * HW + hw;
    const float* wr = w1w + (size_t)o * CC;

    float acc = 0.f;
#pragma unroll 8
    for (int c = 0; c < CC; ++c)
        acc = fmaf(xb[(size_t)c * HW], wr[c], acc);

    float sc = gamma[o] * rsqrtf(var[o] + 1e-5f);
    float sh = beta[o] - mean[o] * sc;
    float v = fmaf(acc, sc, sh);
    g_w1[idx] = v > 0.f ? v : 0.f;
}

// ---------------------------------------------------------------------------
// Kernel 2: w2 = conv2_1x1(w1) + bias   -> [B, G*K2, H, W]
// one thread per output element; inner loop over Cr=64
// ---------------------------------------------------------------------------
__global__ void k2_conv2(const float* __restrict__ w2w,
                         const float* __restrict__ w2b) {
    int idx = blockIdx.x * blockDim.x + threadIdx.x;
    if (idx >= BB * GG * K2 * HW) return;
    int hw = idx % HW;
    int o  = (idx / HW) % (GG * K2);
    int b  = idx / (GG * K2 * HW);

    const float* in = g_w1 + (size_t)b * CR * HW + hw;
    const float* wr = w2w + (size_t)o * CR;

    float acc = w2b[o];
#pragma unroll 8
    for (int c = 0; c < CR; ++c)
        acc = fmaf(in[(size_t)c * HW], wr[c], acc);

    g_w2[idx] = acc;
}

// ---------------------------------------------------------------------------
// Kernel 3: out[b,c,h,w] = sum_{ki,kj} w2[b, g*49 + ki*7+kj, h, w]
//                              * x[b, c, h+ki-3, w+kj-3]  (zero pad)
// ---------------------------------------------------------------------------
__global__ void k3_involution(const float* __restrict__ x,
                              float* __restrict__ out) {
    int idx = blockIdx.x * blockDim.x + threadIdx.x;
    if (idx >= BB * CC * HW) return;
    int hw = idx % HW;
    int w0 = hw % WW;
    int h0 = hw / WW;
    int c  = (idx / HW) % CC;
    int b  = idx / (CC * HW);
    int g  = c / GC;

    const float* wg = g_w2 + ((size_t)(b * GG + g) * K2) * HW + hw;
    const float* xb = x + ((size_t)b * CC + c) * HW;

    float acc = 0.f;
#pragma unroll
    for (int ki = 0; ki < KK; ++ki) {
        int hh = h0 + ki - PAD;
        if (hh < 0 || hh >= HH) continue;
#pragma unroll
        for (int kj = 0; kj < KK; ++kj) {
            int ww = w0 + kj - PAD;
            if (ww < 0 || ww >= WW) continue;
            acc = fmaf(wg[(size_t)(ki * KK + kj) * HW], xb[hh * WW + ww], acc);
        }
    }
    out[idx] = acc;
}

// ---------------------------------------------------------------------------
extern "C" void kernel_launch(void* const* d_in, const int* in_sizes, int n_in,
                              void* d_out, int out_size) {
    const float* x     = (const float*)d_in[0];
    const float* w1w   = (const float*)d_in[1];
    const float* gamma = (const float*)d_in[2];
    const float* beta  = (const float*)d_in[3];
    const float* mean  = (const float*)d_in[4];
    const float* var   = (const float*)d_in[5];
    const float* w2w   = (const float*)d_in[6];
    const float* w2b   = (const float*)d_in[7];
    float* out = (float*)d_out;

    const int T = 256;

    int n1 = BB * CR * HW;
    k1_conv1_bn_relu<<<(n1 + T - 1) / T, T>>>(x, w1w, gamma, beta, mean, var);

    int n2 = BB * GG * K2 * HW;
    k2_conv2<<<(n2 + T - 1) / T, T>>>(w2w, w2b);

    int n3 = BB * CC * HW;
    k3_involution<<<(n3 + T - 1) / T, T>>>(x, out);
}

// round 2
// speedup vs baseline: 3.0453x; 3.0453x over previous
#include <cuda_runtime.h>

#define BB 4
#define CC 256
#define HH 56
#define WW 56
#define CR 64          // C / 4
#define GG 16          // groups
#define GC 16
#define KK 7
#define K2 49
#define M2 (GG * K2)   // 784
#define HW (HH * WW)   // 3136
#define PAD 3

// Scratch (__device__ globals; no allocations allowed)
__device__ float g_w1[BB * CR * HW];        // [B, Cr, HW]
__device__ float g_w2[BB * M2 * HW];        // [B, G*49, HW]

// ---------------------------------------------------------------------------
// K1: w1 = relu(bn(conv1_1x1(x))).  GEMM: [64 x 256] * [256 x HW] per batch.
// Block: 64 (o) x 128 (hw) tile, 256 threads, 8x4 register tile each.
// ---------------------------------------------------------------------------
__global__ __launch_bounds__(256) void k1_conv1_bn_relu(
        const float* __restrict__ x,
        const float* __restrict__ w1w,
        const float* __restrict__ gamma,
        const float* __restrict__ beta,
        const float* __restrict__ mean,
        const float* __restrict__ var) {
    __shared__ float As[64 * 64];    // [o][k]
    __shared__ float Bs[64 * 128];   // [k][hw]

    const int tid = threadIdx.x;
    const int tx = tid & 31;         // hw quad index
    const int ty = tid >> 5;         // o-octet index (warp id)
    const int hw0 = blockIdx.x * 128;
    const int b = blockIdx.y;

    float acc[8][4];
#pragma unroll
    for (int i = 0; i < 8; ++i)
#pragma unroll
        for (int u = 0; u < 4; ++u) acc[i][u] = 0.f;

    for (int kt = 0; kt < CC; kt += 64) {
        // load A tile: 64x64, coalesced along k
#pragma unroll
        for (int r = 0; r < 16; ++r) {
            int idx = tid + r * 256;
            int o = idx >> 6, k = idx & 63;
            As[idx] = w1w[o * CC + kt + k];
        }
        // load B tile: 64x128, coalesced along hw
#pragma unroll
        for (int r = 0; r < 32; ++r) {
            int idx = tid + r * 256;
            int k = idx >> 7, j = idx & 127;
            int hw = hw0 + j;
            Bs[idx] = (hw < HW) ? x[((size_t)(b * CC + kt + k)) * HW + hw] : 0.f;
        }
        __syncthreads();

#pragma unroll
        for (int k = 0; k < 64; ++k) {
            float4 bv = *(const float4*)&Bs[k * 128 + tx * 4];
#pragma unroll
            for (int i = 0; i < 8; ++i) {
                float a = As[(ty * 8 + i) * 64 + k];
                acc[i][0] = fmaf(a, bv.x, acc[i][0]);
                acc[i][1] = fmaf(a, bv.y, acc[i][1]);
                acc[i][2] = fmaf(a, bv.z, acc[i][2]);
                acc[i][3] = fmaf(a, bv.w, acc[i][3]);
            }
        }
        __syncthreads();
    }

    // epilogue: BN(eval) + ReLU
#pragma unroll
    for (int i = 0; i < 8; ++i) {
        int o = ty * 8 + i;
        float sc = gamma[o] * rsqrtf(var[o] + 1e-5f);
        float sh = beta[o] - mean[o] * sc;
        float* dst = g_w1 + ((size_t)(b * CR + o)) * HW;
#pragma unroll
        for (int u = 0; u < 4; ++u) {
            int hw = hw0 + tx * 4 + u;
            if (hw < HW) {
                float v = fmaf(acc[i][u], sc, sh);
                dst[hw] = v > 0.f ? v : 0.f;
            }
        }
    }
}

// ---------------------------------------------------------------------------
// K2: w2 = conv2_1x1(w1) + bias.  GEMM: [784 x 64] * [64 x HW] per batch.
// Same tiling; K=64 single step. M padded to 13 tiles of 64 (guarded).
// ---------------------------------------------------------------------------
__global__ __launch_bounds__(256) void k2_conv2(
        const float* __restrict__ w2w,
        const float* __restrict__ w2b) {
    __shared__ float As[64 * 64];    // [o][k]
    __shared__ float Bs[64 * 128];   // [k][hw]

    const int tid = threadIdx.x;
    const int tx = tid & 31;
    const int ty = tid >> 5;
    const int hw0 = blockIdx.x * 128;
    const int o0 = blockIdx.y * 64;
    const int b = blockIdx.z;

    // load A tile (guard o < 784)
#pragma unroll
    for (int r = 0; r < 16; ++r) {
        int idx = tid + r * 256;
        int o = idx >> 6, k = idx & 63;
        As[idx] = (o0 + o < M2) ? w2w[(o0 + o) * CR + k] : 0.f;
    }
    // load B tile
#pragma unroll
    for (int r = 0; r < 32; ++r) {
        int idx = tid + r * 256;
        int k = idx >> 7, j = idx & 127;
        int hw = hw0 + j;
        Bs[idx] = (hw < HW) ? g_w1[((size_t)(b * CR + k)) * HW + hw] : 0.f;
    }
    __syncthreads();

    float acc[8][4];
#pragma unroll
    for (int i = 0; i < 8; ++i)
#pragma unroll
        for (int u = 0; u < 4; ++u) acc[i][u] = 0.f;

#pragma unroll
    for (int k = 0; k < 64; ++k) {
        float4 bv = *(const float4*)&Bs[k * 128 + tx * 4];
#pragma unroll
        for (int i = 0; i < 8; ++i) {
            float a = As[(ty * 8 + i) * 64 + k];
            acc[i][0] = fmaf(a, bv.x, acc[i][0]);
            acc[i][1] = fmaf(a, bv.y, acc[i][1]);
            acc[i][2] = fmaf(a, bv.z, acc[i][2]);
            acc[i][3] = fmaf(a, bv.w, acc[i][3]);
        }
    }

#pragma unroll
    for (int i = 0; i < 8; ++i) {
        int o = o0 + ty * 8 + i;
        if (o >= M2) continue;
        float bias = w2b[o];
        float* dst = g_w2 + ((size_t)(b * M2 + o)) * HW;
#pragma unroll
        for (int u = 0; u < 4; ++u) {
            int hw = hw0 + tx * 4 + u;
            if (hw < HW) dst[hw] = acc[i][u] + bias;
        }
    }
}

// ---------------------------------------------------------------------------
// K3: involution reduce. One thread per (b, g, pixel), all 16 channels.
// Each tap weight loaded once, reused for 16 FMAs.
// ---------------------------------------------------------------------------
__global__ __launch_bounds__(256) void k3_involution(
        const float* __restrict__ x,
        float* __restrict__ out) {
    int idx = blockIdx.x * blockDim.x + threadIdx.x;
    if (idx >= BB * GG * HW) return;
    int hw = idx % HW;
    int g = (idx / HW) % GG;
    int b = idx / (GG * HW);
    int w0 = hw % WW;
    int h0 = hw / WW;

    const float* wg = g_w2 + ((size_t)(b * GG + g) * K2) * HW + hw;
    const float* xb = x + ((size_t)(b * CC + g * GC)) * HW;

    float acc[GC];
#pragma unroll
    for (int ch = 0; ch < GC; ++ch) acc[ch] = 0.f;

#pragma unroll
    for (int ki = 0; ki < KK; ++ki) {
        int hh = h0 + ki - PAD;
        if (hh < 0 || hh >= HH) continue;
        const float* xr = xb + hh * WW;
#pragma unroll
        for (int kj = 0; kj < KK; ++kj) {
            int ww = w0 + kj - PAD;
            if (ww < 0 || ww >= WW) continue;
            float w = wg[(size_t)(ki * KK + kj) * HW];
#pragma unroll
            for (int ch = 0; ch < GC; ++ch)
                acc[ch] = fmaf(w, xr[(size_t)ch * HW + ww], acc[ch]);
        }
    }

    float* dst = out + ((size_t)(b * CC + g * GC)) * HW + hw;
#pragma unroll
    for (int ch = 0; ch < GC; ++ch)
        dst[(size_t)ch * HW] = acc[ch];
}

// ---------------------------------------------------------------------------
extern "C" void kernel_launch(void* const* d_in, const int* in_sizes, int n_in,
                              void* d_out, int out_size) {
    const float* x     = (const float*)d_in[0];
    const float* w1w   = (const float*)d_in[1];
    const float* gamma = (const float*)d_in[2];
    const float* beta  = (const float*)d_in[3];
    const float* mean  = (const float*)d_in[4];
    const float* var   = (const float*)d_in[5];
    const float* w2w   = (const float*)d_in[6];
    const float* w2b   = (const float*)d_in[7];
    float* out = (float*)d_out;

    dim3 g1((HW + 127) / 128, BB);
    k1_conv1_bn_relu<<<g1, 256>>>(x, w1w, gamma, beta, mean, var);

    dim3 g2((HW + 127) / 128, (M2 + 63) / 64, BB);
    k2_conv2<<<g2, 256>>>(w2w, w2b);

    int n3 = BB * GG * HW;
    k3_involution<<<(n3 + 255) / 256, 256>>>(x, out);
}